// round 7
// baseline (speedup 1.0000x reference)
#include <cuda_runtime.h>

#define BATCH 4
#define SEQ   4096
#define EMBED 768
#define HEAD  64
#define NQB   (SEQ / 64)

// Scratch for projected Q, K, V  (3 x 4 MB). __device__ globals: no allocation.
__device__ float g_Q[BATCH * SEQ * HEAD];
__device__ float g_K[BATCH * SEQ * HEAD];
__device__ float g_V[BATCH * SEQ * HEAD];

// XOR-granule swizzle for [a][b] tiles with 64-float rows.
// Element (a,b) lives at a*64 + (((b>>2) ^ (a>>2)) & 15)*4 + (b&3).
// float4 access at b4 (multiple of 4):
__device__ __forceinline__ int swz4(int a, int b4) {
    return a * 64 + ((((b4 >> 2) ^ (a >> 2)) & 15) << 2);
}
__device__ __forceinline__ int swz1(int a, int b) {
    return swz4(a, b & ~3) + (b & 3);
}

// ---------------------------------------------------------------------------
// QKV projection: out[m][h] = sum_e x[m][e] * W[e][h] + b[h]
// M = BATCH*SEQ = 16384, K = 768, N = 64.  blockIdx.y selects Q/K/V.
// Tiles: 64(M) x 32(K) x 64(N). 256 threads, 4x4 micro-tile per thread.
// ---------------------------------------------------------------------------
__global__ __launch_bounds__(256) void qkv_proj(
    const float* __restrict__ x,
    const float* __restrict__ Wq, const float* __restrict__ bq,
    const float* __restrict__ Wk, const float* __restrict__ bk,
    const float* __restrict__ Wv, const float* __restrict__ bv)
{
    __shared__ float As[32 * 64];   // x tile, transposed: As[k][m] (swizzled)
    __shared__ float Bs[32 * 64];   // W tile: Bs[k][h] (plain)

    const float* W; const float* bias; float* out;
    if (blockIdx.y == 0)      { W = Wq; bias = bq; out = g_Q; }
    else if (blockIdx.y == 1) { W = Wk; bias = bk; out = g_K; }
    else                      { W = Wv; bias = bv; out = g_V; }

    const int tid = threadIdx.x;
    const int ty = tid >> 4;        // 0..15 -> M micro-row
    const int tx = tid & 15;        // 0..15 -> N micro-col
    const int mBase = blockIdx.x * 64;

    float c[4][4] = {};

    for (int k0 = 0; k0 < EMBED; k0 += 32) {
        #pragma unroll
        for (int i = 0; i < 2; i++) {
            int f4 = tid + i * 256;            // 0..511
            // x tile: 64 m-rows x 8 float4 along k
            int m  = f4 >> 3;
            int kq = (f4 & 7) << 2;
            float4 v = *(const float4*)&x[(size_t)(mBase + m) * EMBED + k0 + kq];
            As[swz1(kq + 0, m)] = v.x;
            As[swz1(kq + 1, m)] = v.y;
            As[swz1(kq + 2, m)] = v.z;
            As[swz1(kq + 3, m)] = v.w;
            // W tile: 32 k-rows x 16 float4 along h
            int kk = f4 >> 4;
            int h  = (f4 & 15) << 2;
            *(float4*)&Bs[kk * 64 + h] = *(const float4*)&W[(size_t)(k0 + kk) * HEAD + h];
        }
        __syncthreads();

        #pragma unroll
        for (int kk = 0; kk < 32; kk++) {
            float4 a4 = *(const float4*)&As[swz4(kk, ty << 2)];
            float4 b4 = *(const float4*)&Bs[kk * 64 + (tx << 2)];
            float a[4] = {a4.x, a4.y, a4.z, a4.w};
            float b[4] = {b4.x, b4.y, b4.z, b4.w};
            #pragma unroll
            for (int r = 0; r < 4; r++)
                #pragma unroll
                for (int cc = 0; cc < 4; cc++)
                    c[r][cc] = fmaf(a[r], b[cc], c[r][cc]);
        }
        __syncthreads();
    }

    float4 bb = *(const float4*)&bias[tx << 2];
    float bv4[4] = {bb.x, bb.y, bb.z, bb.w};
    #pragma unroll
    for (int r = 0; r < 4; r++) {
        float4 o = make_float4(c[r][0] + bv4[0], c[r][1] + bv4[1],
                               c[r][2] + bv4[2], c[r][3] + bv4[3]);
        *(float4*)&out[(size_t)(mBase + (ty << 2) + r) * HEAD + (tx << 2)] = o;
    }
}

// ---------------------------------------------------------------------------
// Flash attention, causal. BLOCK_M = BLOCK_N = 64, H = 64.
// 256 threads (16x16), 4x4 micro-tile for S and for the O accumulator.
// smem: Qs (K-major transposed), KPs (K transposed; reused as P^T), Vs.
// Exactly 48 KB static smem -> 2 blocks/SM.
// ---------------------------------------------------------------------------
__global__ __launch_bounds__(256) void attn(float* __restrict__ out)
{
    __shared__ float Qs [64 * 64];   // Qs[h][r]  (swizzled)
    __shared__ float KPs[64 * 64];   // Ks[h][j]  -> later P^T[j][r]
    __shared__ float Vs [64 * 64];   // Vs[j][h]  (swizzled)

    const int b   = blockIdx.y;
    const int qb  = NQB - 1 - blockIdx.x;   // heavy blocks first
    const int tid = threadIdx.x;
    const int ty  = tid >> 4;               // query micro-row group
    const int tx  = tid & 15;               // key / head micro-col group

    const float* Qg = g_Q + ((size_t)b * SEQ + (size_t)qb * 64) * HEAD;
    const float* Kg = g_K + (size_t)b * SEQ * HEAD;
    const float* Vg = g_V + (size_t)b * SEQ * HEAD;

    // Load Q tile transposed: Qs[h][r]
    #pragma unroll
    for (int i = 0; i < 4; i++) {
        int f4 = tid + i * 256;          // 0..1023
        int r  = f4 >> 4;                // query row in tile
        int h4 = (f4 & 15) << 2;
        float4 v = *(const float4*)&Qg[(size_t)r * HEAD + h4];
        Qs[swz1(h4 + 0, r)] = v.x;
        Qs[swz1(h4 + 1, r)] = v.y;
        Qs[swz1(h4 + 2, r)] = v.z;
        Qs[swz1(h4 + 3, r)] = v.w;
    }

    float m_r[4], l_r[4], acc[4][4];
    #pragma unroll
    for (int r = 0; r < 4; r++) {
        m_r[r] = -1e30f; l_r[r] = 0.0f;
        #pragma unroll
        for (int cc = 0; cc < 4; cc++) acc[r][cc] = 0.0f;
    }

    const float SCALE = 0.125f;   // 1/sqrt(64)

    for (int kb = 0; kb <= qb; kb++) {
        const float* Kt = Kg + (size_t)kb * 64 * HEAD;
        const float* Vt = Vg + (size_t)kb * 64 * HEAD;

        __syncthreads();   // prev PV reads (and Q store on iter 0) complete
        #pragma unroll
        for (int i = 0; i < 4; i++) {
            int f4 = tid + i * 256;
            int r  = f4 >> 4;            // key row in tile
            int h4 = (f4 & 15) << 2;
            float4 kv = *(const float4*)&Kt[(size_t)r * HEAD + h4];
            KPs[swz1(h4 + 0, r)] = kv.x;
            KPs[swz1(h4 + 1, r)] = kv.y;
            KPs[swz1(h4 + 2, r)] = kv.z;
            KPs[swz1(h4 + 3, r)] = kv.w;
            float4 vv = *(const float4*)&Vt[(size_t)r * HEAD + h4];
            *(float4*)&Vs[swz4(r, h4)] = vv;
        }
        __syncthreads();

        // S = (Q K^T) for this tile, in registers
        float s[4][4] = {};
        #pragma unroll
        for (int kk = 0; kk < HEAD; kk++) {
            float4 q4 = *(const float4*)&Qs [swz4(kk, ty << 2)];
            float4 k4 = *(const float4*)&KPs[swz4(kk, tx << 2)];
            float qa[4] = {q4.x, q4.y, q4.z, q4.w};
            float ka[4] = {k4.x, k4.y, k4.z, k4.w};
            #pragma unroll
            for (int r = 0; r < 4; r++)
                #pragma unroll
                for (int cc = 0; cc < 4; cc++)
                    s[r][cc] = fmaf(qa[r], ka[cc], s[r][cc]);
        }

        // scale + causal mask (diagonal tile only)
        if (kb == qb) {
            #pragma unroll
            for (int r = 0; r < 4; r++)
                #pragma unroll
                for (int cc = 0; cc < 4; cc++) {
                    int trow = (ty << 2) + r, tcol = (tx << 2) + cc;
                    s[r][cc] = (tcol <= trow) ? s[r][cc] * SCALE : -1e30f;
                }
        } else {
            #pragma unroll
            for (int r = 0; r < 4; r++)
                #pragma unroll
                for (int cc = 0; cc < 4; cc++) s[r][cc] *= SCALE;
        }

        // online softmax per row (rows live in 16-lane groups: same ty)
        #pragma unroll
        for (int r = 0; r < 4; r++) {
            float m0 = fmaxf(fmaxf(s[r][0], s[r][1]), fmaxf(s[r][2], s[r][3]));
            #pragma unroll
            for (int off = 8; off > 0; off >>= 1)
                m0 = fmaxf(m0, __shfl_xor_sync(0xffffffffu, m0, off));
            float newm  = fmaxf(m_r[r], m0);
            float alpha = __expf(m_r[r] - newm);
            float lsum  = 0.0f;
            #pragma unroll
            for (int cc = 0; cc < 4; cc++) {
                float e = __expf(s[r][cc] - newm);
                s[r][cc] = e;                 // s becomes P
                lsum += e;
            }
            #pragma unroll
            for (int off = 8; off > 0; off >>= 1)
                lsum += __shfl_xor_sync(0xffffffffu, lsum, off);
            l_r[r] = l_r[r] * alpha + lsum;
            m_r[r] = newm;
            #pragma unroll
            for (int cc = 0; cc < 4; cc++) acc[r][cc] *= alpha;
        }

        __syncthreads();   // all K reads done; KPs now becomes P^T
        #pragma unroll
        for (int cc = 0; cc < 4; cc++) {
            int j = (tx << 2) + cc;
            float4 v = make_float4(s[0][cc], s[1][cc], s[2][cc], s[3][cc]);
            *(float4*)&KPs[swz4(j, ty << 2)] = v;   // P^T[j][r0..r0+3]
        }
        __syncthreads();

        // O += P V
        #pragma unroll
        for (int j = 0; j < 64; j++) {
            float4 p4 = *(const float4*)&KPs[swz4(j, ty << 2)];
            float4 v4 = *(const float4*)&Vs [swz4(j, tx << 2)];
            float pa[4] = {p4.x, p4.y, p4.z, p4.w};
            float va[4] = {v4.x, v4.y, v4.z, v4.w};
            #pragma unroll
            for (int r = 0; r < 4; r++)
                #pragma unroll
                for (int cc = 0; cc < 4; cc++)
                    acc[r][cc] = fmaf(pa[r], va[cc], acc[r][cc]);
        }
    }

    // epilogue: normalize and store
    float* Og = out + ((size_t)b * SEQ + (size_t)qb * 64) * HEAD;
    #pragma unroll
    for (int r = 0; r < 4; r++) {
        float inv = 1.0f / l_r[r];
        float4 o = make_float4(acc[r][0] * inv, acc[r][1] * inv,
                               acc[r][2] * inv, acc[r][3] * inv);
        *(float4*)&Og[(size_t)((ty << 2) + r) * HEAD + (tx << 2)] = o;
    }
}

// ---------------------------------------------------------------------------
extern "C" void kernel_launch(void* const* d_in, const int* in_sizes, int n_in,
                              void* d_out, int out_size)
{
    const float* x  = (const float*)d_in[0];
    const float* Wq = (const float*)d_in[1];
    const float* bq = (const float*)d_in[2];
    const float* Wk = (const float*)d_in[3];
    const float* bk = (const float*)d_in[4];
    const float* Wv = (const float*)d_in[5];
    const float* bv = (const float*)d_in[6];
    float* out = (float*)d_out;

    dim3 gp((BATCH * SEQ) / 64, 3);
    qkv_proj<<<gp, 256>>>(x, Wq, bq, Wk, bk, Wv, bv);

    dim3 ga(NQB, BATCH);
    attn<<<ga, 256>>>(out);
}